// round 14
// baseline (speedup 1.0000x reference)
#include <cuda_runtime.h>
#include <cuda_fp16.h>
#include <math.h>
#include <stdint.h>

// B=2, H=16, S=2048, DK=64
// Inputs: Q[B,H,S,DK] f32, K[B,H,S,DK] f32, V[B,H,S,DK] f32, mask[B,1,S,S] i32
// Output: concat( O[B,H,S,DK] f32, W[B,H,S,S] f32 )

#define BATCH 2
#define HEADS 16
#define SEQ   2048
#define DKDIM 64
#define NELEM ((size_t)BATCH * HEADS * SEQ * DKDIM)       // 4,194,304
#define NMASK ((size_t)BATCH * SEQ * SEQ)                 // 8,388,608

#define HST 72   // half-element stride (144B rows; cp.async aligned, ldmatrix conflict-free)

// 0.125 * log2(e)
#define SCALE_L2E 0.18033688011112042f

__device__ __half g_Qh[NELEM];
__device__ __half g_Kh[NELEM];
__device__ __half g_Vh[NELEM];
__device__ __half g_Mh[NMASK];                            // mask as fp16 {0,1}

// ---------------------------------------------------------------------------
__device__ __forceinline__ uint32_t pack2(float a, float b) {
    __half2 h = __floats2half2_rn(a, b);
    return *(uint32_t*)&h;
}

__device__ __forceinline__ float fexp2(float x) {
    float y;
    asm("ex2.approx.ftz.f32 %0, %1;" : "=f"(y) : "f"(x));
    return y;
}

__device__ __forceinline__ void cp16(void* smem, const void* gmem) {
    uint32_t s = (uint32_t)__cvta_generic_to_shared(smem);
    asm volatile("cp.async.cg.shared.global [%0], [%1], 16;" :: "r"(s), "l"(gmem));
}
__device__ __forceinline__ void cp_commit() {
    asm volatile("cp.async.commit_group;");
}
__device__ __forceinline__ void cp_wait0() {
    asm volatile("cp.async.wait_group 0;");
}

__device__ __forceinline__ void ldsm4(uint32_t r[4], const __half* p) {
    uint32_t addr = (uint32_t)__cvta_generic_to_shared(p);
    asm volatile("ldmatrix.sync.aligned.m8n8.x4.shared.b16 {%0,%1,%2,%3}, [%4];"
                 : "=r"(r[0]), "=r"(r[1]), "=r"(r[2]), "=r"(r[3]) : "r"(addr));
}
__device__ __forceinline__ void ldsm4t(uint32_t r[4], const __half* p) {
    uint32_t addr = (uint32_t)__cvta_generic_to_shared(p);
    asm volatile("ldmatrix.sync.aligned.m8n8.x4.trans.shared.b16 {%0,%1,%2,%3}, [%4];"
                 : "=r"(r[0]), "=r"(r[1]), "=r"(r[2]), "=r"(r[3]) : "r"(addr));
}
__device__ __forceinline__ void mma_f16(float c[4], const uint32_t a[4],
                                        uint32_t b0, uint32_t b1) {
    asm volatile(
        "mma.sync.aligned.m16n8k16.row.col.f32.f16.f16.f32 "
        "{%0,%1,%2,%3}, {%4,%5,%6,%7}, {%8,%9}, {%0,%1,%2,%3};\n"
        : "+f"(c[0]), "+f"(c[1]), "+f"(c[2]), "+f"(c[3])
        : "r"(a[0]), "r"(a[1]), "r"(a[2]), "r"(a[3]), "r"(b0), "r"(b1));
}

// ---------------------------------------------------------------------------
// Pre-convert Q/K/V f32 -> fp16.
// ---------------------------------------------------------------------------
__global__ __launch_bounds__(256)
void convert_kernel(const float* __restrict__ Q,
                    const float* __restrict__ K,
                    const float* __restrict__ V)
{
    const size_t i = ((size_t)blockIdx.x * 256 + threadIdx.x) * 8;
    {
        float4 a = *(const float4*)(Q + i), b = *(const float4*)(Q + i + 4);
        uint4 u = { pack2(a.x, a.y), pack2(a.z, a.w), pack2(b.x, b.y), pack2(b.z, b.w) };
        *(uint4*)(g_Qh + i) = u;
    }
    {
        float4 a = *(const float4*)(K + i), b = *(const float4*)(K + i + 4);
        uint4 u = { pack2(a.x, a.y), pack2(a.z, a.w), pack2(b.x, b.y), pack2(b.z, b.w) };
        *(uint4*)(g_Kh + i) = u;
    }
    {
        float4 a = *(const float4*)(V + i), b = *(const float4*)(V + i + 4);
        uint4 u = { pack2(a.x, a.y), pack2(a.z, a.w), pack2(b.x, b.y), pack2(b.z, b.w) };
        *(uint4*)(g_Vh + i) = u;
    }
}

// Mask int32 -> fp16 {0,1}
__global__ __launch_bounds__(256)
void maskconv_kernel(const int* __restrict__ mask)
{
    const size_t i = ((size_t)blockIdx.x * 256 + threadIdx.x) * 8;
    int4 a = *(const int4*)(mask + i);
    int4 b = *(const int4*)(mask + i + 4);
    uint4 u;
    u.x = pack2(a.x ? 1.f : 0.f, a.y ? 1.f : 0.f);
    u.y = pack2(a.z ? 1.f : 0.f, a.w ? 1.f : 0.f);
    u.z = pack2(b.x ? 1.f : 0.f, b.y ? 1.f : 0.f);
    u.w = pack2(b.z ? 1.f : 0.f, b.w ? 1.f : 0.f);
    *(uint4*)(g_Mh + i) = u;
}

// ---------------------------------------------------------------------------
// Single fused kernel (recompute scheme). 8 warps, each owns a 16-row q strip.
//  Loop1 (K only): mma1 S=QK^T, e=ex2(S*c)*m, accumulate rowsums. No stores.
//  inv = 1/rowsum (warp-private).
//  Loop2 (K+V):   mma1 recomputed, p = e*inv -> STG f32 W (normalized, final),
//                 mma2 accO += p @ V (A-frags from registers). O = accO.
// One block sync per iteration (cp.async double buffers).
// ---------------------------------------------------------------------------
__global__ __launch_bounds__(256, 2)
void sdpa_fused_kernel(float* __restrict__ W,
                       float* __restrict__ O)
{
    extern __shared__ __align__(16) char smraw[];
    __half* Qs = (__half*)smraw;              // [128][HST]
    __half* Ks = Qs + 128 * HST;              // [2][64][HST]
    __half* Vs = Ks + 2 * 64 * HST;           // [2][64][HST]

    const int bh   = blockIdx.y;
    const int b    = bh >> 4;
    const int q0   = blockIdx.x * 128;
    const int tid  = threadIdx.x;
    const int lane = tid & 31;
    const int warp = tid >> 5;    // 0..7, owns q rows [warp*16, +16)
    const int gid  = lane >> 2;   // 0..7
    const int tig  = lane & 3;    // 0..3

    const __half* Qp = g_Qh + ((size_t)bh * SEQ + q0) * DKDIM;
    const __half* Kp = g_Kh + (size_t)bh * SEQ * DKDIM;
    const __half* Vp = g_Vh + (size_t)bh * SEQ * DKDIM;

    const int crow = tid >> 3;   // 0..31
    const int cgrp = tid & 7;

    // ldmatrix lane patterns
    const int a_row  = (lane & 15);
    const int a_col  = (lane >> 4) << 3;
    const int bk_row = ((lane >> 4) << 3) + (lane & 7);
    const int bk_col = ((lane >> 3) & 1) << 3;
    const int bv_row = (((lane >> 3) & 1) << 3) + (lane & 7);
    const int bv_col = (lane >> 4) << 3;

    // per-thread global row bases
    const int rl0 = warp * 16 + gid;
    const int rl1 = rl0 + 8;
    const __half* mrow0 = g_Mh + ((size_t)b * SEQ + q0 + rl0) * SEQ;
    const __half* mrow1 = g_Mh + ((size_t)b * SEQ + q0 + rl1) * SEQ;

    // ---------------- prologue: Q + K0 ----------------
    #pragma unroll
    for (int it = 0; it < 4; it++) {
        const int id  = tid + it * 256;
        const int row = id >> 3;
        cp16(Qs + row * HST + cgrp * 8, Qp + row * DKDIM + cgrp * 8);
    }
    #pragma unroll
    for (int it = 0; it < 2; it++) {
        const int row = crow + 32 * it;
        cp16(Ks + row * HST + cgrp * 8, Kp + (size_t)row * DKDIM + cgrp * 8);
    }
    cp_commit();

    float rsum0 = 0.f, rsum1 = 0.f;

    // ================= LOOP 1: rowsums (K only) =================
    for (int kt = 0; kt < 32; kt++) {
        const int buf = kt & 1;

        cp_wait0();
        __syncthreads();

        if (kt + 1 < 32) {
            const int nb = (kt + 1) & 1;
            const __half* Kn = Kp + (size_t)(kt + 1) * 64 * DKDIM;
            #pragma unroll
            for (int it = 0; it < 2; it++) {
                const int row = crow + 32 * it;
                cp16(Ks + (nb * 64 + row) * HST + cgrp * 8, Kn + (size_t)row * DKDIM + cgrp * 8);
            }
            cp_commit();
        }

        const __half* Kb = Ks + buf * 64 * HST;

        float accS[8][4];
        #pragma unroll
        for (int j = 0; j < 8; j++)
            #pragma unroll
            for (int t = 0; t < 4; t++) accS[j][t] = 0.f;

        #pragma unroll
        for (int d0 = 0; d0 < DKDIM; d0 += 16) {
            uint32_t a[4];
            ldsm4(a, Qs + (warp * 16 + a_row) * HST + d0 + a_col);
            #pragma unroll
            for (int nb = 0; nb < 4; nb++) {
                uint32_t bb[4];
                ldsm4(bb, Kb + (nb * 16 + bk_row) * HST + d0 + bk_col);
                mma_f16(accS[nb * 2 + 0], a, bb[0], bb[1]);
                mma_f16(accS[nb * 2 + 1], a, bb[2], bb[3]);
            }
        }

        const __half* m0 = mrow0 + kt * 64;
        const __half* m1 = mrow1 + kt * 64;
        #pragma unroll
        for (int j = 0; j < 8; j++) {
            const int c = j * 8 + 2 * tig;
            const uint32_t mm0 = *(const uint32_t*)(m0 + c);
            const uint32_t mm1 = *(const uint32_t*)(m1 + c);
            float2 mf0 = __half22float2(*(const __half2*)&mm0);
            float2 mf1 = __half22float2(*(const __half2*)&mm1);
            rsum0 += fexp2(accS[j][0] * SCALE_L2E) * mf0.x
                   + fexp2(accS[j][1] * SCALE_L2E) * mf0.y;
            rsum1 += fexp2(accS[j][2] * SCALE_L2E) * mf1.x
                   + fexp2(accS[j][3] * SCALE_L2E) * mf1.y;
        }
    }

    // ---- warp-private rowsums -> inv ----
    rsum0 += __shfl_xor_sync(0xffffffffu, rsum0, 1);
    rsum0 += __shfl_xor_sync(0xffffffffu, rsum0, 2);
    rsum1 += __shfl_xor_sync(0xffffffffu, rsum1, 1);
    rsum1 += __shfl_xor_sync(0xffffffffu, rsum1, 2);
    const float inv0 = 1.0f / rsum0;
    const float inv1 = 1.0f / rsum1;

    // ---------------- preload K0 + V0 for loop 2 ----------------
    // Safe: Ks buf0 last read at kt=30 (before kt=31's barrier); Vs untouched.
    #pragma unroll
    for (int it = 0; it < 2; it++) {
        const int row = crow + 32 * it;
        cp16(Ks + row * HST + cgrp * 8, Kp + (size_t)row * DKDIM + cgrp * 8);
        cp16(Vs + row * HST + cgrp * 8, Vp + (size_t)row * DKDIM + cgrp * 8);
    }
    cp_commit();

    float accO[8][4];
    #pragma unroll
    for (int j = 0; j < 8; j++)
        #pragma unroll
        for (int t = 0; t < 4; t++) accO[j][t] = 0.f;

    float* wrow0 = W + ((size_t)bh * SEQ + q0 + rl0) * SEQ;
    float* wrow1 = W + ((size_t)bh * SEQ + q0 + rl1) * SEQ;

    // ================= LOOP 2: W + O =================
    for (int kt = 0; kt < 32; kt++) {
        const int buf = kt & 1;

        cp_wait0();
        __syncthreads();

        if (kt + 1 < 32) {
            const int nb = (kt + 1) & 1;
            const __half* Kn = Kp + (size_t)(kt + 1) * 64 * DKDIM;
            const __half* Vn = Vp + (size_t)(kt + 1) * 64 * DKDIM;
            #pragma unroll
            for (int it = 0; it < 2; it++) {
                const int row = crow + 32 * it;
                cp16(Ks + (nb * 64 + row) * HST + cgrp * 8, Kn + (size_t)row * DKDIM + cgrp * 8);
                cp16(Vs + (nb * 64 + row) * HST + cgrp * 8, Vn + (size_t)row * DKDIM + cgrp * 8);
            }
            cp_commit();
        }

        const __half* Kb = Ks + buf * 64 * HST;
        const __half* Vb = Vs + buf * 64 * HST;

        // ---- mma1: S = Q @ K^T ----
        float accS[8][4];
        #pragma unroll
        for (int j = 0; j < 8; j++)
            #pragma unroll
            for (int t = 0; t < 4; t++) accS[j][t] = 0.f;

        #pragma unroll
        for (int d0 = 0; d0 < DKDIM; d0 += 16) {
            uint32_t a[4];
            ldsm4(a, Qs + (warp * 16 + a_row) * HST + d0 + a_col);
            #pragma unroll
            for (int nb = 0; nb < 4; nb++) {
                uint32_t bb[4];
                ldsm4(bb, Kb + (nb * 16 + bk_row) * HST + d0 + bk_col);
                mma_f16(accS[nb * 2 + 0], a, bb[0], bb[1]);
                mma_f16(accS[nb * 2 + 1], a, bb[2], bb[3]);
            }
        }

        // ---- per 16-k chunk: epilogue (normalized W write) + mma2 ----
        const __half* m0 = mrow0 + kt * 64;
        const __half* m1 = mrow1 + kt * 64;
        float* w0p = wrow0 + kt * 64;
        float* w1p = wrow1 + kt * 64;
        #pragma unroll
        for (int cch = 0; cch < 4; cch++) {
            uint32_t a[4];
            #pragma unroll
            for (int jj = 0; jj < 2; jj++) {
                const int j = 2 * cch + jj;
                const int c = j * 8 + 2 * tig;
                const uint32_t mm0 = *(const uint32_t*)(m0 + c);
                const uint32_t mm1 = *(const uint32_t*)(m1 + c);
                float2 mf0 = __half22float2(*(const __half2*)&mm0);
                float2 mf1 = __half22float2(*(const __half2*)&mm1);
                float p00 = fexp2(accS[j][0] * SCALE_L2E) * mf0.x * inv0;
                float p01 = fexp2(accS[j][1] * SCALE_L2E) * mf0.y * inv0;
                float p10 = fexp2(accS[j][2] * SCALE_L2E) * mf1.x * inv1;
                float p11 = fexp2(accS[j][3] * SCALE_L2E) * mf1.y * inv1;
                *(float2*)(w0p + c) = make_float2(p00, p01);
                *(float2*)(w1p + c) = make_float2(p10, p11);
                a[jj * 2 + 0] = pack2(p00, p01);   // wait: frag order fixed below
                a[jj * 2 + 1] = pack2(p10, p11);
            }
            // A-frag order for m16n8k16: {row r, k0..1}, {row r+8, k0..1},
            // {row r, k8..9}, {row r+8, k8..9} -> a = {lo(j0), hi(j0), lo(j1), hi(j1)}
            // built above as a[0]=lo j0, a[1]=hi j0, a[2]=lo j1, a[3]=hi j1. Correct.
            const int k0 = cch * 16;
            #pragma unroll
            for (int nb = 0; nb < 4; nb++) {
                uint32_t bb[4];
                ldsm4t(bb, Vb + (k0 + bv_row) * HST + nb * 16 + bv_col);
                mma_f16(accO[nb * 2 + 0], a, bb[0], bb[1]);
                mma_f16(accO[nb * 2 + 1], a, bb[2], bb[3]);
            }
        }
    }

    // ---- store O (already normalized) ----
    float* orow0 = O + ((size_t)bh * SEQ + q0 + rl0) * DKDIM;
    float* orow1 = O + ((size_t)bh * SEQ + q0 + rl1) * DKDIM;
    #pragma unroll
    for (int j = 0; j < 8; j++) {
        const int c = j * 8 + 2 * tig;
        float2 v0 = { accO[j][0], accO[j][1] };
        float2 v1 = { accO[j][2], accO[j][3] };
        *(float2*)(orow0 + c) = v0;
        *(float2*)(orow1 + c) = v1;
    }
}

// ---------------------------------------------------------------------------
extern "C" void kernel_launch(void* const* d_in, const int* in_sizes, int n_in,
                              void* d_out, int out_size)
{
    const float* Q    = (const float*)d_in[0];
    const float* K    = (const float*)d_in[1];
    const float* V    = (const float*)d_in[2];
    const int*   mask = (const int*)  d_in[3];

    float* O = (float*)d_out;                                        // [B,H,S,DK]
    float* W = (float*)d_out + (size_t)BATCH * HEADS * SEQ * DKDIM;  // [B,H,S,S]

    const int smem = (128 * HST + 2 * 64 * HST + 2 * 64 * HST) * 2;  // 55,296 B
    cudaFuncSetAttribute(sdpa_fused_kernel,
                         cudaFuncAttributeMaxDynamicSharedMemorySize, smem);

    {
        convert_kernel<<<NELEM / (256 * 8), 256>>>(Q, K, V);
        maskconv_kernel<<<NMASK / (256 * 8), 256>>>(mask);
    }
    {
        dim3 grid(SEQ / 128, BATCH * HEADS);
        sdpa_fused_kernel<<<grid, 256, smem>>>(W, O);
    }
}